// round 16
// baseline (speedup 1.0000x reference)
#include <cuda_runtime.h>

#define NPTS  8192
#define KNN   32
#define NEDGE (NPTS*KNN)        // 262144
#define NOUT  64
#define QB    8                 // queries per knn group
#define NGRP  (NPTS/QB)         // 1024 query groups
#define KGRID 888               // persistent knn blocks (6/SM x 148 SM)
#define CAPQ  192               // survivor capacity per query (22-sigma headroom)
#define COLCAP_S 256            // colmat smem rank-by-count capacity
#define COLCAP_G 512            // per-node incoming-edge buffer capacity
#define TMARGIN 0.01f           // proxy-threshold safety margin

// float32 concat layout of the 4-tuple output
#define OFF_ROW ((NEDGE+1)*NOUT)                  // 16777280
#define OFF_COL (OFF_ROW + (NEDGE+1)*KNN)         // 25165920
#define OFF_IJ  (OFF_COL + (NEDGE+1)*KNN)         // 33554560

#define IQUADS  ((NEDGE+1)*8)

__device__ float4 g_pts[NPTS];               // {x, y, z, x2}
__device__ float  g_bcoef[NOUT];             // log2(e) / (2*sigma_c^2)
__device__ float  g_knn_d2[NEDGE];
__device__ int    g_counts[NPTS];
__device__ int    g_incoming[NPTS*COLCAP_G]; // per-target incoming edge ids
__device__ int    g_work;                    // persistent-knn work counter

// exact reference fp32 distance:
// dot = fma(z, fma(y, rn(x*x))) ; d2 = rn(rn(x2i+x2j) - rn(2*dot)) ; clamp 0
__device__ __forceinline__ float ref_d2(const float4 q, const float4 c){
    float dot = __fmul_rn(q.x, c.x);
    dot = __fmaf_rn(q.y, c.y, dot);
    dot = __fmaf_rn(q.z, c.z, dot);
    float t = __fadd_rn(q.w, c.w);
    float v = __fmaf_rn(-2.0f, dot, t);   // == rn(t - rn(2*dot)); 2*dot exact
    return fmaxf(v, 0.0f);
}

// 3-FMA proxy: u = -2qx*cx -2qy*cy -2qz*cz + x2j  ~= d2 - x2i  (+-5e-4)
__device__ __forceinline__ float proxy_u(const float4 m, const float4 c){
    return __fmaf_rn(m.x, c.x, __fmaf_rn(m.y, c.y, __fmaf_rn(m.z, c.z, c.w)));
}

// monotone float -> uint (handles negatives) for unsigned ranking
__device__ __forceinline__ unsigned f2mono(float f){
    unsigned b = __float_as_uint(f);
    return b ^ (((int)b >> 31) | 0x80000000u);
}

// ---------------------------------------------------------------- prep
// x2 = ((rn(x0^2) + rn(x1^2)) + rn(x2^2))  -- XLA mul + sequential reduce
__global__ void prep_kernel(const float* __restrict__ coord){
    int j = blockIdx.x*blockDim.x + threadIdx.x;
    if (j < NPTS){
        float a = coord[3*j+0], b = coord[3*j+1], c = coord[3*j+2];
        float s0 = __fmul_rn(a,a);
        float s1 = __fmul_rn(b,b);
        float s2 = __fmul_rn(c,c);
        float x2 = __fadd_rn(__fadd_rn(s0,s1), s2);
        g_pts[j] = make_float4(a, b, c, x2);
        g_counts[j] = 0;
    }
    if (j < NOUT){
        float sig = 0.1f + (float)j * (4.9f/63.0f);
        g_bcoef[j] = 1.4426950408889634f / (2.0f*sig*sig);
    }
    if (j == 0) g_work = 0;
}

// ---------------------------------------------------------------- dummy
// no-op; occupies the profiled launch slot so ncu captures knn_kernel next
__global__ void dummy_kernel(){ }

// ---------------------------------------------------------------- KNN (+ k matrix), persistent
// Work-queue over 1024 query groups (8 queries each); grid = 888 = 6/SM so
// the whole kernel is one balanced wave (kills the 1.15-wave tail).
//  Pass 1: per-thread min of proxy u over 32 candidates, per query.
//  Threshold (warp q): T = 32nd-smallest of 64 group-mins (4-thread groups,
//    each covering 128 disjoint candidates => >=32 survivors u<=T), +margin.
//  Pass 2: recompute proxies (kept in regs), single branch per candidate;
//    survivors get exact ref_d2 (query rebuilt exactly as q = -0.5*M).
//  Phase D: warp w ranks query w's survivors (rank-by-counting, LDS broadcast).
//  Phase E: dense (32 x 64) k tiles via MUFU ex2, coalesced float4 stores.
__global__ void __launch_bounds__(256, 6) knn_kernel(float* __restrict__ out){
    const int tid  = threadIdx.x;
    const int lane = tid & 31;
    const int wid  = tid >> 5;

    __shared__ int   s_grp;
    __shared__ float s_min[QB*256];
    __shared__ float s_T[QB];
    __shared__ int   s_cnt[QB];
    __shared__ unsigned long long s_key[QB*CAPQ];
    __shared__ float s_d2[QB][KNN];

    const float4* __restrict__ p = g_pts + tid;

    for (;;){
        if (tid == 0) s_grp = atomicAdd(&g_work, 1);
        __syncthreads();
        const int grp = s_grp;
        if (grp >= NGRP) return;
        const int i0 = grp * QB;

        if (tid < QB) s_cnt[tid] = 0;

        float4 M[QB];
        float  x2i[QB];
#pragma unroll
        for (int q = 0; q < QB; q++){
            float4 Qv = g_pts[i0 + q];
            M[q]  = make_float4(-2.0f*Qv.x, -2.0f*Qv.y, -2.0f*Qv.z, 0.f);
            x2i[q] = Qv.w;
        }

        // ---- Pass 1: per-thread proxy min per query
        float tmin[QB];
#pragma unroll
        for (int q = 0; q < QB; q++) tmin[q] = 3.4e38f;
#pragma unroll 8
        for (int s = 0; s < 32; s++){
            float4 c = p[s*256];
#pragma unroll
            for (int q = 0; q < QB; q++)
                tmin[q] = fminf(tmin[q], proxy_u(M[q], c));
        }
#pragma unroll
        for (int q = 0; q < QB; q++) s_min[q*256 + tid] = tmin[q];
        __syncthreads();

        // ---- Threshold: warp w handles query w. 64 groups of 4 threads.
        {
            const int q = wid;
            const float* sm = s_min + q*256;
            float ga = fminf(fminf(sm[lane*4+0], sm[lane*4+1]),
                             fminf(sm[lane*4+2], sm[lane*4+3]));
            float gb = fminf(fminf(sm[128+lane*4+0], sm[128+lane*4+1]),
                             fminf(sm[128+lane*4+2], sm[128+lane*4+3]));
            unsigned long long ka = (((unsigned long long)f2mono(ga)) << 6) | (unsigned)lane;
            unsigned long long kb = (((unsigned long long)f2mono(gb)) << 6) | (unsigned)(lane+32);
            unsigned long long* gk = s_key + q*CAPQ;   // scratch (dead after T)
            gk[lane]      = ka;
            gk[lane + 32] = kb;
            __syncwarp();
            int ra = 0, rb = 0;
#pragma unroll
            for (int k = 0; k < 64; k++){
                unsigned long long o = gk[k];
                ra += (o < ka);
                rb += (o < kb);
            }
            if (ra == 31) s_T[q] = ga;
            if (rb == 31) s_T[q] = gb;
        }
        __syncthreads();

        float Tq[QB];
#pragma unroll
        for (int q = 0; q < QB; q++) Tq[q] = s_T[q] + TMARGIN;

        // ---- Pass 2: proxy scan, one branch per candidate; survivors exact
#pragma unroll 8
        for (int s = 0; s < 32; s++){
            float4 c = p[s*256];
            float u[QB];
            float m = 3.4e38f;
#pragma unroll
            for (int q = 0; q < QB; q++){
                u[q] = proxy_u(M[q], c);
                m = fminf(m, u[q] - Tq[q]);
            }
            if (m <= 0.0f){
                unsigned j = (unsigned)(s*256 + tid);
#pragma unroll
                for (int q = 0; q < QB; q++){
                    if (u[q] <= Tq[q]){
                        // exact reference query operands: q = -0.5*M (exact)
                        float4 qv = make_float4(__fmul_rn(-0.5f, M[q].x),
                                                __fmul_rn(-0.5f, M[q].y),
                                                __fmul_rn(-0.5f, M[q].z),
                                                x2i[q]);
                        float d2 = ref_d2(qv, c);   // exact reference value
                        int pos = atomicAdd(&s_cnt[q], 1);
                        if (pos < CAPQ)
                            s_key[q*CAPQ + pos] =
                                (((unsigned long long)__float_as_uint(d2)) << 32) | j;
                    }
                }
            }
        }
        __syncthreads();

        // ---- Phase D: warp w ranks query w (keys unique via j). Order-invariant.
        {
            const int q = wid;
            int cnt = min(s_cnt[q], CAPQ);
            const unsigned long long* keys = s_key + q*CAPQ;
            for (int s0 = lane; s0 < cnt; s0 += 32){
                unsigned long long my = keys[s0];
                int rank = 0;
                for (int k = 0; k < cnt; k++) rank += (keys[k] < my);  // LDS broadcast
                if (rank < KNN){
                    int   j  = (int)(unsigned)(my & 0xffffffffULL);
                    float d2 = __uint_as_float((unsigned)(my >> 32));
                    int e = (i0 + q)*KNN + rank;
                    g_knn_d2[e]    = d2;
                    s_d2[q][rank]  = d2;
                    int pos = atomicAdd(&g_counts[j], 1);
                    if (pos < COLCAP_G) g_incoming[j*COLCAP_G + pos] = e;
                    out[OFF_IJ + 2*e + 0] = (float)(i0 + q);
                    out[OFF_IJ + 2*e + 1] = (float)j;
                }
            }
        }
        __syncthreads();

        // ---- Phase E: dense k-tile fill. Per query: 32 rows x 64 cols =
        // 512 quads; 256 threads x 2 quads. Coalesced float4 stores.
#pragma unroll
        for (int q = 0; q < QB; q++){
            unsigned rowbase = (unsigned)(i0 + q)*KNN + 1;
#pragma unroll
            for (int h = 0; h < 2; h++){
                int qq  = tid + h*256;        // 0..511
                int row = qq >> 4;
                int c4  = (qq & 15) << 2;
                float d2 = s_d2[q][row];
                const float4 b = *(const float4*)&g_bcoef[c4];
                float4 v;
                asm("ex2.approx.ftz.f32 %0, %1;" : "=f"(v.x) : "f"(-d2*b.x));
                asm("ex2.approx.ftz.f32 %0, %1;" : "=f"(v.y) : "f"(-d2*b.y));
                asm("ex2.approx.ftz.f32 %0, %1;" : "=f"(v.z) : "f"(-d2*b.z));
                asm("ex2.approx.ftz.f32 %0, %1;" : "=f"(v.w) : "f"(-d2*b.w));
                *(float4*)&out[(rowbase + row)*NOUT + c4] = v;
            }
        }
        __syncthreads();
    }
}

// ---------------------------------------------------------------- colmat + col_idx expansion (fused)
// One warp per target node t. Build its 32-entry colmat row:
//   count <= 32: key = e            (stable edge-id order, zero-pad tail)
//   count  > 32: key = (d2bits, e)  (lexsort by distance, tie by edge id)
// then write the 32 repeated col_idx output rows directly (float4 stores).
__global__ void __launch_bounds__(256) colmat_kernel(float* __restrict__ out){
    __shared__ unsigned long long s_ck[8][COLCAP_S];
    __shared__ float s_val[8][KNN];
    int gw   = (blockIdx.x*blockDim.x + threadIdx.x) >> 5;
    int lane = threadIdx.x & 31;
    int wloc = (threadIdx.x >> 5);
    if (gw >= NPTS) return;
    int t   = gw;
    int cnt = g_counts[t];
    bool heavy = cnt > KNN;
    const int* inc = g_incoming + t*COLCAP_G;

    s_val[wloc][lane] = 0.0f;
    __syncwarp();

    if (cnt <= COLCAP_S){
        for (int s = lane; s < cnt; s += 32){
            int e = inc[s];
            unsigned long long key;
            if (heavy) key = (((unsigned long long)__float_as_uint(g_knn_d2[e])) << 32) | (unsigned)e;
            else       key = (unsigned long long)(unsigned)e;
            s_ck[wloc][s] = key;
        }
        __syncwarp();
        for (int s = lane; s < cnt; s += 32){
            unsigned long long my = s_ck[wloc][s];
            int rank = 0;
            for (int k = 0; k < cnt; k++) rank += (s_ck[wloc][k] < my);
            if (rank < KNN){
                unsigned e = heavy ? (unsigned)(my & 0xffffffffULL) : (unsigned)my;
                s_val[wloc][rank] = (float)((int)e + 1);
            }
        }
        __syncwarp();
    } else {
        // rare fallback (256 < cnt <= 512): serial extract-min, order-invariant
        int cc = min(cnt, COLCAP_G);
        unsigned long long pk = 0ULL;
        unsigned long long mk = ~0ULL;
        for (int s = lane; s < cc; s += 32){
            int e = inc[s];
            unsigned long long key = (((unsigned long long)__float_as_uint(g_knn_d2[e])) << 32) | (unsigned)e;
            key += 1ULL;
            if (key < mk) mk = key;
        }
        for (int r = 0; r < 32; r++){
            unsigned long long rk = mk;
            for (int o = 16; o; o >>= 1){
                unsigned long long ok = __shfl_xor_sync(0xffffffffu, rk, o);
                if (ok < rk) rk = ok;
            }
            if (lane == 0 && rk != ~0ULL)
                s_val[wloc][r] = (float)((int)(unsigned)((rk - 1ULL) & 0xffffffffULL) + 1);
            if (mk == rk && rk != ~0ULL){
                pk = rk;
                mk = ~0ULL;
                for (int s = lane; s < cc; s += 32){
                    int e = inc[s];
                    unsigned long long key = (((unsigned long long)__float_as_uint(g_knn_d2[e])) << 32) | (unsigned)e;
                    key += 1ULL;
                    if (key > pk && key < mk) mk = key;
                }
            }
        }
        __syncwarp();
    }

    // write 32 output rows (rows t*32+1 .. t*32+32), 8 float4 per row
    const float4* src = (const float4*)(&s_val[wloc][0]);
#pragma unroll
    for (int kq = 0; kq < 8; kq++){
        int lin  = lane + 32*kq;       // 0..255
        int row  = lin >> 3;
        int quad = lin & 7;
        *(float4*)&out[OFF_COL + (unsigned)(t*KNN + row + 1)*KNN + quad*4] = src[quad];
    }
}

// ---------------------------------------------------------------- row_idx fill (no dependencies)
// also zeroes row 0 of the col_idx region and row 0 of the k region
__global__ void rowfill_kernel(float* __restrict__ out){
    int idx = blockIdx.x*blockDim.x + threadIdx.x;
    if (idx < IQUADS){
        int r = idx >> 3;
        int qc = (idx & 7) << 2;
        float4 rv = make_float4(0.f,0.f,0.f,0.f);
        if (r > 0){
            int e = r - 1;
            int k = (e & ~31) + qc;
            rv = make_float4((float)k, (float)(k+1), (float)(k+2), (float)(k+3));
        }
        *(float4*)&out[OFF_ROW + (idx << 2)] = rv;
    } else if (idx < IQUADS + 8){
        *(float4*)&out[OFF_COL + ((idx - IQUADS) << 2)] =
            make_float4(0.f,0.f,0.f,0.f);
    } else if (idx < IQUADS + 8 + 16){
        *(float4*)&out[(idx - IQUADS - 8) << 2] =      // k row 0
            make_float4(0.f,0.f,0.f,0.f);
    }
}

// ---------------------------------------------------------------- launch
// DAG (graph-capturable multi-stream fork/join):
//   main:  prep -> dummy -> knn(+k, persistent 888) -> colmat(+col_idx)
//   s2:    rowfill (independent), joined at the end
// dummy keeps knn in ncu's profiled launch slot.
extern "C" void kernel_launch(void* const* d_in, const int* in_sizes, int n_in,
                              void* d_out, int out_size){
    const float* coord = (const float*)d_in[0];
    float* out = (float*)d_out;

    static cudaStream_t s2 = nullptr;
    static cudaEvent_t  evA = nullptr, evC = nullptr;
    if (s2 == nullptr){
        cudaStreamCreateWithFlags(&s2, cudaStreamNonBlocking);
        cudaEventCreateWithFlags(&evA, cudaEventDisableTiming);
        cudaEventCreateWithFlags(&evC, cudaEventDisableTiming);
    }

    // fork: s2 branches off the main (capture-origin) stream
    cudaEventRecord(evA, (cudaStream_t)0);
    cudaStreamWaitEvent(s2, evA, 0);

    rowfill_kernel<<<(IQUADS + 8 + 16 + 255)/256, 256, 0, s2>>>(out);
    cudaEventRecord(evC, s2);

    prep_kernel  <<<(NPTS+255)/256, 256>>>(coord);
    dummy_kernel <<<1, 32>>>();
    knn_kernel   <<<KGRID, 256>>>(out);
    colmat_kernel<<<NPTS/8, 256>>>(out);

    // join
    cudaStreamWaitEvent((cudaStream_t)0, evC, 0);
}

// round 17
// speedup vs baseline: 1.9747x; 1.9747x over previous
#include <cuda_runtime.h>

#define NPTS  8192
#define KNN   32
#define NEDGE (NPTS*KNN)        // 262144
#define NOUT  64
#define QB    8                 // queries per knn group
#define NGRP  (NPTS/QB)         // 1024 query groups
#define CAPQ  192               // survivor capacity per query (22-sigma headroom)
#define COLCAP_S 256            // colmat smem rank-by-count capacity
#define COLCAP_G 512            // per-node incoming-edge buffer capacity
#define TMARGIN 0.01f           // proxy-threshold safety margin

// float32 concat layout of the 4-tuple output
#define OFF_ROW ((NEDGE+1)*NOUT)                  // 16777280
#define OFF_COL (OFF_ROW + (NEDGE+1)*KNN)         // 25165920
#define OFF_IJ  (OFF_COL + (NEDGE+1)*KNN)         // 33554560

#define IQUADS  ((NEDGE+1)*8)

__device__ float4 g_pts[NPTS];               // {x, y, z, x2}
__device__ float  g_bcoef[NOUT];             // log2(e) / (2*sigma_c^2)
__device__ float  g_knn_d2[NEDGE];
__device__ int    g_counts[NPTS];
__device__ int    g_incoming[NPTS*COLCAP_G]; // per-target incoming edge ids
__device__ int    g_work;                    // persistent-knn work counter

// exact reference fp32 distance:
// dot = fma(z, fma(y, rn(x*x))) ; d2 = rn(rn(x2i+x2j) - rn(2*dot)) ; clamp 0
__device__ __forceinline__ float ref_d2(const float4 q, const float4 c){
    float dot = __fmul_rn(q.x, c.x);
    dot = __fmaf_rn(q.y, c.y, dot);
    dot = __fmaf_rn(q.z, c.z, dot);
    float t = __fadd_rn(q.w, c.w);
    float v = __fmaf_rn(-2.0f, dot, t);   // == rn(t - rn(2*dot)); 2*dot exact
    return fmaxf(v, 0.0f);
}

// 3-FMA proxy: u = -2qx*cx -2qy*cy -2qz*cz + x2j  ~= d2 - x2i  (+-5e-4)
__device__ __forceinline__ float proxy_u(const float4 m, const float4 c){
    return __fmaf_rn(m.x, c.x, __fmaf_rn(m.y, c.y, __fmaf_rn(m.z, c.z, c.w)));
}

// monotone float -> uint (handles negatives) for unsigned ranking
__device__ __forceinline__ unsigned f2mono(float f){
    unsigned b = __float_as_uint(f);
    return b ^ (((int)b >> 31) | 0x80000000u);
}

// ---------------------------------------------------------------- prep
// x2 = ((rn(x0^2) + rn(x1^2)) + rn(x2^2))  -- XLA mul + sequential reduce
__global__ void prep_kernel(const float* __restrict__ coord){
    int j = blockIdx.x*blockDim.x + threadIdx.x;
    if (j < NPTS){
        float a = coord[3*j+0], b = coord[3*j+1], c = coord[3*j+2];
        float s0 = __fmul_rn(a,a);
        float s1 = __fmul_rn(b,b);
        float s2 = __fmul_rn(c,c);
        float x2 = __fadd_rn(__fadd_rn(s0,s1), s2);
        g_pts[j] = make_float4(a, b, c, x2);
        g_counts[j] = 0;
    }
    if (j < NOUT){
        float sig = 0.1f + (float)j * (4.9f/63.0f);
        g_bcoef[j] = 1.4426950408889634f / (2.0f*sig*sig);
    }
    if (j == 0) g_work = 0;
}

// ---------------------------------------------------------------- dummy
// no-op; occupies the profiled launch slot so ncu captures knn_kernel next
__global__ void dummy_kernel(){ }

// ---------------------------------------------------------------- KNN (+ k matrix), persistent
// Work-queue over 1024 query groups (8 queries each); grid sized at runtime
// to exactly fill residency (occupancy query x SM count) -> single balanced
// wave, no tail. Otherwise identical to the R15 kernel (best: 86.1us).
//  Pass 1: per-thread min of proxy u over 32 candidates, per query.
//  Threshold (warp q): T = 32nd-smallest of 64 group-mins (4-thread groups,
//    each covering 128 disjoint candidates => >=32 survivors u<=T), +margin.
//  Pass 2: recompute proxy; survivors get exact ref_d2 (query reconstructed
//    exactly as q = -0.5*M, both scalings exact); compact as keys.
//  Phase D: warp w ranks query w's survivors (rank-by-counting, LDS broadcast).
//  Phase E: dense (32 x 64) k tiles via MUFU ex2, coalesced float4 stores.
__global__ void __launch_bounds__(256) knn_kernel(float* __restrict__ out){
    const int tid  = threadIdx.x;
    const int lane = tid & 31;
    const int wid  = tid >> 5;

    __shared__ int   s_grp;
    __shared__ float s_min[QB*256];
    __shared__ float s_T[QB];
    __shared__ int   s_cnt[QB];
    __shared__ unsigned long long s_key[QB*CAPQ];
    __shared__ float s_d2[QB][KNN];

    const float4* __restrict__ p = g_pts + tid;

    for (;;){
        if (tid == 0) s_grp = atomicAdd(&g_work, 1);
        __syncthreads();
        const int grp = s_grp;
        if (grp >= NGRP) return;
        const int i0 = grp * QB;

        if (tid < QB) s_cnt[tid] = 0;

        float4 M[QB];
        float  x2i[QB];
#pragma unroll
        for (int q = 0; q < QB; q++){
            float4 Qv = g_pts[i0 + q];
            M[q]  = make_float4(-2.0f*Qv.x, -2.0f*Qv.y, -2.0f*Qv.z, 0.f);
            x2i[q] = Qv.w;
        }

        // ---- Pass 1: per-thread proxy min per query
        float tmin[QB];
#pragma unroll
        for (int q = 0; q < QB; q++) tmin[q] = 3.4e38f;
#pragma unroll 8
        for (int s = 0; s < 32; s++){
            float4 c = p[s*256];
#pragma unroll
            for (int q = 0; q < QB; q++)
                tmin[q] = fminf(tmin[q], proxy_u(M[q], c));
        }
#pragma unroll
        for (int q = 0; q < QB; q++) s_min[q*256 + tid] = tmin[q];
        __syncthreads();

        // ---- Threshold: warp w handles query w. 64 groups of 4 threads.
        {
            const int q = wid;
            const float* sm = s_min + q*256;
            float ga = fminf(fminf(sm[lane*4+0], sm[lane*4+1]),
                             fminf(sm[lane*4+2], sm[lane*4+3]));
            float gb = fminf(fminf(sm[128+lane*4+0], sm[128+lane*4+1]),
                             fminf(sm[128+lane*4+2], sm[128+lane*4+3]));
            unsigned long long ka = (((unsigned long long)f2mono(ga)) << 6) | (unsigned)lane;
            unsigned long long kb = (((unsigned long long)f2mono(gb)) << 6) | (unsigned)(lane+32);
            unsigned long long* gk = s_key + q*CAPQ;   // scratch (dead after T)
            gk[lane]      = ka;
            gk[lane + 32] = kb;
            __syncwarp();
            int ra = 0, rb = 0;
#pragma unroll
            for (int k = 0; k < 64; k++){
                unsigned long long o = gk[k];
                ra += (o < ka);
                rb += (o < kb);
            }
            if (ra == 31) s_T[q] = ga;
            if (rb == 31) s_T[q] = gb;
        }
        __syncthreads();

        float Tq[QB];
#pragma unroll
        for (int q = 0; q < QB; q++) Tq[q] = s_T[q] + TMARGIN;

        // ---- Pass 2: proxy scan; survivors get exact d2 and are compacted
#pragma unroll 8
        for (int s = 0; s < 32; s++){
            float4 c = p[s*256];
            unsigned j = (unsigned)(s*256 + tid);
#pragma unroll
            for (int q = 0; q < QB; q++){
                float u = proxy_u(M[q], c);
                if (u <= Tq[q]){
                    // exact reference query operands: q = -0.5 * M (both exact)
                    float4 qv = make_float4(__fmul_rn(-0.5f, M[q].x),
                                            __fmul_rn(-0.5f, M[q].y),
                                            __fmul_rn(-0.5f, M[q].z),
                                            x2i[q]);
                    float d2 = ref_d2(qv, c);       // exact reference value
                    int pos = atomicAdd(&s_cnt[q], 1);
                    if (pos < CAPQ)
                        s_key[q*CAPQ + pos] =
                            (((unsigned long long)__float_as_uint(d2)) << 32) | j;
                }
            }
        }
        __syncthreads();

        // ---- Phase D: warp w ranks query w (keys unique via j). Order-invariant.
        {
            const int q = wid;
            int cnt = min(s_cnt[q], CAPQ);
            const unsigned long long* keys = s_key + q*CAPQ;
            for (int s0 = lane; s0 < cnt; s0 += 32){
                unsigned long long my = keys[s0];
                int rank = 0;
                for (int k = 0; k < cnt; k++) rank += (keys[k] < my);  // LDS broadcast
                if (rank < KNN){
                    int   j  = (int)(unsigned)(my & 0xffffffffULL);
                    float d2 = __uint_as_float((unsigned)(my >> 32));
                    int e = (i0 + q)*KNN + rank;
                    g_knn_d2[e]    = d2;
                    s_d2[q][rank]  = d2;
                    int pos = atomicAdd(&g_counts[j], 1);
                    if (pos < COLCAP_G) g_incoming[j*COLCAP_G + pos] = e;
                    out[OFF_IJ + 2*e + 0] = (float)(i0 + q);
                    out[OFF_IJ + 2*e + 1] = (float)j;
                }
            }
        }
        __syncthreads();

        // ---- Phase E: dense k-tile fill. Per query: 32 rows x 64 cols =
        // 512 quads; 256 threads x 2 quads. Coalesced float4 stores.
#pragma unroll
        for (int q = 0; q < QB; q++){
            unsigned rowbase = (unsigned)(i0 + q)*KNN + 1;
#pragma unroll
            for (int h = 0; h < 2; h++){
                int qq  = tid + h*256;        // 0..511
                int row = qq >> 4;
                int c4  = (qq & 15) << 2;
                float d2 = s_d2[q][row];
                const float4 b = *(const float4*)&g_bcoef[c4];
                float4 v;
                asm("ex2.approx.ftz.f32 %0, %1;" : "=f"(v.x) : "f"(-d2*b.x));
                asm("ex2.approx.ftz.f32 %0, %1;" : "=f"(v.y) : "f"(-d2*b.y));
                asm("ex2.approx.ftz.f32 %0, %1;" : "=f"(v.z) : "f"(-d2*b.z));
                asm("ex2.approx.ftz.f32 %0, %1;" : "=f"(v.w) : "f"(-d2*b.w));
                *(float4*)&out[(rowbase + row)*NOUT + c4] = v;
            }
        }
        __syncthreads();
    }
}

// ---------------------------------------------------------------- colmat + col_idx expansion (fused)
// One warp per target node t. Build its 32-entry colmat row:
//   count <= 32: key = e            (stable edge-id order, zero-pad tail)
//   count  > 32: key = (d2bits, e)  (lexsort by distance, tie by edge id)
// then write the 32 repeated col_idx output rows directly (float4 stores).
__global__ void __launch_bounds__(256) colmat_kernel(float* __restrict__ out){
    __shared__ unsigned long long s_ck[8][COLCAP_S];
    __shared__ float s_val[8][KNN];
    int gw   = (blockIdx.x*blockDim.x + threadIdx.x) >> 5;
    int lane = threadIdx.x & 31;
    int wloc = (threadIdx.x >> 5);
    if (gw >= NPTS) return;
    int t   = gw;
    int cnt = g_counts[t];
    bool heavy = cnt > KNN;
    const int* inc = g_incoming + t*COLCAP_G;

    s_val[wloc][lane] = 0.0f;
    __syncwarp();

    if (cnt <= COLCAP_S){
        for (int s = lane; s < cnt; s += 32){
            int e = inc[s];
            unsigned long long key;
            if (heavy) key = (((unsigned long long)__float_as_uint(g_knn_d2[e])) << 32) | (unsigned)e;
            else       key = (unsigned long long)(unsigned)e;
            s_ck[wloc][s] = key;
        }
        __syncwarp();
        for (int s = lane; s < cnt; s += 32){
            unsigned long long my = s_ck[wloc][s];
            int rank = 0;
            for (int k = 0; k < cnt; k++) rank += (s_ck[wloc][k] < my);
            if (rank < KNN){
                unsigned e = heavy ? (unsigned)(my & 0xffffffffULL) : (unsigned)my;
                s_val[wloc][rank] = (float)((int)e + 1);
            }
        }
        __syncwarp();
    } else {
        // rare fallback (256 < cnt <= 512): serial extract-min, order-invariant
        int cc = min(cnt, COLCAP_G);
        unsigned long long pk = 0ULL;
        unsigned long long mk = ~0ULL;
        for (int s = lane; s < cc; s += 32){
            int e = inc[s];
            unsigned long long key = (((unsigned long long)__float_as_uint(g_knn_d2[e])) << 32) | (unsigned)e;
            key += 1ULL;
            if (key < mk) mk = key;
        }
        for (int r = 0; r < 32; r++){
            unsigned long long rk = mk;
            for (int o = 16; o; o >>= 1){
                unsigned long long ok = __shfl_xor_sync(0xffffffffu, rk, o);
                if (ok < rk) rk = ok;
            }
            if (lane == 0 && rk != ~0ULL)
                s_val[wloc][r] = (float)((int)(unsigned)((rk - 1ULL) & 0xffffffffULL) + 1);
            if (mk == rk && rk != ~0ULL){
                pk = rk;
                mk = ~0ULL;
                for (int s = lane; s < cc; s += 32){
                    int e = inc[s];
                    unsigned long long key = (((unsigned long long)__float_as_uint(g_knn_d2[e])) << 32) | (unsigned)e;
                    key += 1ULL;
                    if (key > pk && key < mk) mk = key;
                }
            }
        }
        __syncwarp();
    }

    // write 32 output rows (rows t*32+1 .. t*32+32), 8 float4 per row
    const float4* src = (const float4*)(&s_val[wloc][0]);
#pragma unroll
    for (int kq = 0; kq < 8; kq++){
        int lin  = lane + 32*kq;       // 0..255
        int row  = lin >> 3;
        int quad = lin & 7;
        *(float4*)&out[OFF_COL + (unsigned)(t*KNN + row + 1)*KNN + quad*4] = src[quad];
    }
}

// ---------------------------------------------------------------- row_idx fill (no dependencies)
// also zeroes row 0 of the col_idx region and row 0 of the k region
__global__ void rowfill_kernel(float* __restrict__ out){
    int idx = blockIdx.x*blockDim.x + threadIdx.x;
    if (idx < IQUADS){
        int r = idx >> 3;
        int qc = (idx & 7) << 2;
        float4 rv = make_float4(0.f,0.f,0.f,0.f);
        if (r > 0){
            int e = r - 1;
            int k = (e & ~31) + qc;
            rv = make_float4((float)k, (float)(k+1), (float)(k+2), (float)(k+3));
        }
        *(float4*)&out[OFF_ROW + (idx << 2)] = rv;
    } else if (idx < IQUADS + 8){
        *(float4*)&out[OFF_COL + ((idx - IQUADS) << 2)] =
            make_float4(0.f,0.f,0.f,0.f);
    } else if (idx < IQUADS + 8 + 16){
        *(float4*)&out[(idx - IQUADS - 8) << 2] =      // k row 0
            make_float4(0.f,0.f,0.f,0.f);
    }
}

// ---------------------------------------------------------------- launch
// DAG (graph-capturable multi-stream fork/join):
//   main:  prep -> dummy -> knn(+k, persistent, residency-sized) -> colmat
//   s2:    rowfill (independent), joined at the end
// Grid for knn computed once (uncaptured correctness call) from the
// occupancy API: exact residency => one balanced wave, no tail.
extern "C" void kernel_launch(void* const* d_in, const int* in_sizes, int n_in,
                              void* d_out, int out_size){
    const float* coord = (const float*)d_in[0];
    float* out = (float*)d_out;

    static cudaStream_t s2 = nullptr;
    static cudaEvent_t  evA = nullptr, evC = nullptr;
    static int kgrid = 0;
    if (s2 == nullptr){
        cudaStreamCreateWithFlags(&s2, cudaStreamNonBlocking);
        cudaEventCreateWithFlags(&evA, cudaEventDisableTiming);
        cudaEventCreateWithFlags(&evC, cudaEventDisableTiming);
        int nb = 0, nsm = 0;
        cudaOccupancyMaxActiveBlocksPerMultiprocessor(&nb, knn_kernel, 256, 0);
        cudaDeviceGetAttribute(&nsm, cudaDevAttrMultiProcessorCount, 0);
        if (nb < 1) nb = 1;
        kgrid = nb * nsm;
        if (kgrid > NGRP) kgrid = NGRP;
    }

    // fork: s2 branches off the main (capture-origin) stream
    cudaEventRecord(evA, (cudaStream_t)0);
    cudaStreamWaitEvent(s2, evA, 0);

    rowfill_kernel<<<(IQUADS + 8 + 16 + 255)/256, 256, 0, s2>>>(out);
    cudaEventRecord(evC, s2);

    prep_kernel  <<<(NPTS+255)/256, 256>>>(coord);
    dummy_kernel <<<1, 32>>>();
    knn_kernel   <<<kgrid, 256>>>(out);
    colmat_kernel<<<NPTS/8, 256>>>(out);

    // join
    cudaStreamWaitEvent((cudaStream_t)0, evC, 0);
}